// round 5
// baseline (speedup 1.0000x reference)
#include <cuda_runtime.h>
#include <cstdint>
#include <cstdio>

#define BB 64
#define TT 1024
#define II 256
#define HH 512
#define G4 2048
#define NCTA 128          // persistent CTAs (<=148 SMs, 1 CTA/SM -> co-resident)
#define NC 16             // gate columns per CTA (= 4 h-cols x 4 gates)
#define VT_S 516          // smem strides (== 4 mod 32 -> conflict-free frags)
#define HS_S 516
#define GS_S 18
#define REC_SMEM_FLOATS (NC*VT_S + 64*HS_S + 64*GS_S)
#define REC_SMEM_BYTES (REC_SMEM_FLOATS * 4)

// -------- global scratch (static device memory; no runtime allocation) -----
__device__ float g_xproj[(size_t)BB * TT * G4];   // [t*64+b][2048], bias folded
__device__ float g_hbuf[2][BB * HH];              // h ping-pong (step t reads buf[t&1])
__device__ int   g_pub[NCTA];                     // publish epochs

// -------- helpers -----------------------------------------------------------
__device__ __forceinline__ float tf32r(float f) {
    unsigned u; asm("cvt.rna.tf32.f32 %0, %1;" : "=r"(u) : "f"(f));
    return __uint_as_float(u);
}
__device__ __forceinline__ unsigned fb(float f) { return __float_as_uint(f); }

__device__ __forceinline__ void mma_tf32(float* c,
    unsigned a0, unsigned a1, unsigned a2, unsigned a3, unsigned b0, unsigned b1) {
    asm volatile(
        "mma.sync.aligned.m16n8k8.row.col.f32.tf32.tf32.f32 "
        "{%0,%1,%2,%3},{%4,%5,%6,%7},{%8,%9},{%0,%1,%2,%3};"
        : "+f"(c[0]), "+f"(c[1]), "+f"(c[2]), "+f"(c[3])
        : "r"(a0), "r"(a1), "r"(a2), "r"(a3), "r"(b0), "r"(b1));
}
__device__ __forceinline__ int ld_acq(const int* p) {
    int v; asm volatile("ld.acquire.gpu.s32 %0, [%1];" : "=r"(v) : "l"(p) : "memory");
    return v;
}
__device__ __forceinline__ void st_rel(int* p, int v) {
    asm volatile("st.release.gpu.s32 [%0], %1;" :: "l"(p), "r"(v) : "memory");
}

// -------- reset (state must be reinitialized on every graph replay) ---------
__global__ void reset_kernel() {
    int tid = threadIdx.x + blockIdx.x * blockDim.x;
    for (int i = tid; i < BB * HH; i += blockDim.x * gridDim.x) g_hbuf[0][i] = 0.0f;
    if (blockIdx.x == 0 && threadIdx.x < NCTA) g_pub[threadIdx.x] = 0;
}

// -------- phase 1: g_xproj[r][n] = x @ [U_i|U_f|U_h|U_o] + b ---------------
// row r = t*64+b.  CTA tile 128x64, 8 warps (4M x 2N), warp tile 32x32, tf32.
__global__ void __launch_bounds__(256) xproj_kernel(
    const float* __restrict__ x,
    const float* __restrict__ Ui, const float* __restrict__ Uf,
    const float* __restrict__ Uh, const float* __restrict__ Uo,
    const float* __restrict__ bi, const float* __restrict__ bf,
    const float* __restrict__ bh, const float* __restrict__ bo)
{
    __shared__ float As[128 * 36];
    __shared__ float Bs[32 * 72];
    __shared__ float bias_s[64];

    const int tid = threadIdx.x;
    const int n0 = blockIdx.x * 64;      // gate-col tile base (never crosses a gate)
    const int m0 = blockIdx.y * 128;
    const int q  = n0 >> 9;
    const int c0 = n0 & 511;

    const float* Uq = (q == 0) ? Ui : (q == 1) ? Uf : (q == 2) ? Uh : Uo;
    const float* bq = (q == 0) ? bi : (q == 1) ? bf : (q == 2) ? bh : bo;
    if (tid < 64) bias_s[tid] = bq[c0 + tid];

    const int w = tid >> 5, lane = tid & 31, g = lane >> 2, tig = lane & 3;
    const int warpM = w >> 1, warpN = w & 1;

    const int arow = tid >> 1, ahalf = tid & 1;
    const int r  = m0 + arow;
    const int bbi = r & 63, tti = r >> 6;
    const float* xrow = x + ((size_t)bbi * TT + tti) * II;
    const int brow = tid >> 3, bcol8 = (tid & 7) * 8;

    float acc[2][4][4] = {};

    for (int kc = 0; kc < 8; ++kc) {
        const int k0 = kc * 32;
        #pragma unroll
        for (int i = 0; i < 4; ++i) {
            float4 v = *(const float4*)(xrow + k0 + ahalf * 16 + i * 4);
            int off = arow * 36 + ahalf * 16 + i * 4;
            As[off+0] = tf32r(v.x); As[off+1] = tf32r(v.y);
            As[off+2] = tf32r(v.z); As[off+3] = tf32r(v.w);
        }
        #pragma unroll
        for (int i = 0; i < 2; ++i) {
            float4 v = *(const float4*)(Uq + (size_t)(k0 + brow) * HH + c0 + bcol8 + i * 4);
            int off = brow * 72 + bcol8 + i * 4;
            Bs[off+0] = tf32r(v.x); Bs[off+1] = tf32r(v.y);
            Bs[off+2] = tf32r(v.z); Bs[off+3] = tf32r(v.w);
        }
        __syncthreads();

        #pragma unroll
        for (int kk = 0; kk < 32; kk += 8) {
            unsigned a[2][4];
            #pragma unroll
            for (int i2 = 0; i2 < 2; ++i2) {
                int rb = warpM * 32 + i2 * 16;
                a[i2][0] = fb(As[(rb + g    ) * 36 + kk + tig]);
                a[i2][1] = fb(As[(rb + g + 8) * 36 + kk + tig]);
                a[i2][2] = fb(As[(rb + g    ) * 36 + kk + tig + 4]);
                a[i2][3] = fb(As[(rb + g + 8) * 36 + kk + tig + 4]);
            }
            #pragma unroll
            for (int nt = 0; nt < 4; ++nt) {
                int nn = warpN * 32 + nt * 8 + g;
                unsigned b0 = fb(Bs[(kk + tig    ) * 72 + nn]);
                unsigned b1 = fb(Bs[(kk + tig + 4) * 72 + nn]);
                mma_tf32(acc[0][nt], a[0][0], a[0][1], a[0][2], a[0][3], b0, b1);
                mma_tf32(acc[1][nt], a[1][0], a[1][1], a[1][2], a[1][3], b0, b1);
            }
        }
        __syncthreads();
    }

    #pragma unroll
    for (int i2 = 0; i2 < 2; ++i2) {
        #pragma unroll
        for (int nt = 0; nt < 4; ++nt) {
            int coll = warpN * 32 + nt * 8 + 2 * tig;
            float b0v = bias_s[coll], b1v = bias_s[coll + 1];
            int row0 = m0 + warpM * 32 + i2 * 16 + g;
            *(float2*)&g_xproj[(size_t)row0 * G4 + n0 + coll] =
                make_float2(acc[i2][nt][0] + b0v, acc[i2][nt][1] + b1v);
            *(float2*)&g_xproj[(size_t)(row0 + 8) * G4 + n0 + coll] =
                make_float2(acc[i2][nt][2] + b0v, acc[i2][nt][3] + b1v);
        }
    }
}

// -------- phase 2: persistent recurrence ------------------------------------
__global__ void __launch_bounds__(256, 1) lstm_rec_kernel(
    const float* __restrict__ Vi, const float* __restrict__ Vf,
    const float* __restrict__ Vh, const float* __restrict__ Vo)
{
    extern __shared__ float sm[];
    float* Vt = sm;                  // [16][516] tf32 V slice, [n][k]
    float* hs = Vt + NC * VT_S;      // [64][516] staged h (tf32)
    float* gs = hs + 64 * HS_S;      // [64][18] gate exchange

    const int tid = threadIdx.x, cta = blockIdx.x;
    const int hc0 = cta * 4;
    const int w = tid >> 5, lane = tid & 31, g = lane >> 2, tig = lane & 3;

    // load V slice once: n = gate*4 + hc
    {
        const float* Vq[4] = { Vi, Vf, Vh, Vo };
        for (int idx = tid; idx < NC * HH; idx += 256) {
            int n = idx >> 9, k = idx & 511;
            Vt[n * VT_S + k] = tf32r(Vq[n >> 2][(size_t)k * HH + hc0 + (n & 3)]);
        }
    }

    const int sb = tid >> 2, shc = tid & 3;     // this thread's (batch, hcol) state
    const int srow = tid >> 2, sseg = tid & 3;  // h staging assignment
    float c_state = 0.0f;
    __syncthreads();

    for (int t = 0; t < TT; ++t) {
        // prefetch xproj for this step (independent of h -> hides DRAM latency)
        float xp[4];
        {
            const float* xb = g_xproj + ((size_t)t * BB + sb) * G4 + hc0 + shc;
            #pragma unroll
            for (int q2 = 0; q2 < 4; ++q2) xp[q2] = __ldg(xb + q2 * HH);
        }
        // wait: all CTAs have published h_t (t=0: buf[0] zeroed by reset)
        if (t > 0) {
            if (tid < NCTA) { while (ld_acq(&g_pub[tid]) < t) { } }
        }
        __syncthreads();

        // stage h_t into smem, tf32-rounded
        {
            const float* hb = g_hbuf[t & 1] + srow * HH + sseg * 128;
            float* hd = hs + srow * HS_S + sseg * 128;
            #pragma unroll
            for (int i = 0; i < 32; ++i) {
                float4 v = __ldcg((const float4*)(hb + i * 4));
                hd[i*4+0] = tf32r(v.x); hd[i*4+1] = tf32r(v.y);
                hd[i*4+2] = tf32r(v.z); hd[i*4+3] = tf32r(v.w);
            }
        }
        __syncthreads();

        // gates_hV = h @ Vslice : warps 0..3, warp tile 16(M) x 16(N)
        if (w < 4) {
            float acc[2][4] = {};
            const float* Ab = hs + (w * 16) * HS_S;
            #pragma unroll 4
            for (int kk = 0; kk < 512; kk += 8) {
                unsigned a0 = fb(Ab[(g    ) * HS_S + kk + tig]);
                unsigned a1 = fb(Ab[(g + 8) * HS_S + kk + tig]);
                unsigned a2 = fb(Ab[(g    ) * HS_S + kk + tig + 4]);
                unsigned a3 = fb(Ab[(g + 8) * HS_S + kk + tig + 4]);
                #pragma unroll
                for (int nt = 0; nt < 2; ++nt) {
                    unsigned b0 = fb(Vt[(nt * 8 + g) * VT_S + kk + tig]);
                    unsigned b1 = fb(Vt[(nt * 8 + g) * VT_S + kk + tig + 4]);
                    mma_tf32(acc[nt], a0, a1, a2, a3, b0, b1);
                }
            }
            #pragma unroll
            for (int nt = 0; nt < 2; ++nt) {
                int col = nt * 8 + 2 * tig;
                *(float2*)&gs[(w * 16 + g    ) * GS_S + col] = make_float2(acc[nt][0], acc[nt][1]);
                *(float2*)&gs[(w * 16 + g + 8) * GS_S + col] = make_float2(acc[nt][2], acc[nt][3]);
            }
        }
        __syncthreads();

        // elementwise gate update for state (sb, shc); c lives in a register
        {
            float gi = gs[sb * GS_S + 0 * 4 + shc] + xp[0];
            float gf = gs[sb * GS_S + 1 * 4 + shc] + xp[1];
            float gg = gs[sb * GS_S + 2 * 4 + shc] + xp[2];
            float go = gs[sb * GS_S + 3 * 4 + shc] + xp[3];
            float it = 1.0f / (1.0f + expf(-gi));
            float ft = 1.0f / (1.0f + expf(-gf));
            float gt = tanhf(gg);
            float ot = 1.0f / (1.0f + expf(-go));
            c_state = ft * c_state + it * gt;
            g_hbuf[(t + 1) & 1][sb * HH + hc0 + shc] = ot * tanhf(c_state);
        }
        __threadfence();
        __syncthreads();
        if (tid == 0) st_rel(&g_pub[cta], t + 1);
    }
}

// -------- phase 3: out[b] = h_last . fc_w + fc_b ----------------------------
__global__ void fc_kernel(const float* __restrict__ fc_w,
                          const float* __restrict__ fc_b, float* out) {
    int b = blockIdx.x, tid = threadIdx.x;
    const float* h = g_hbuf[0] + b * HH;   // h_1024 lives in buf[(1023+1)&1] = buf[0]
    float s = 0.0f;
    for (int k = tid; k < HH; k += 128) s += h[k] * fc_w[k];
    #pragma unroll
    for (int o = 16; o; o >>= 1) s += __shfl_down_sync(0xFFFFFFFFu, s, o);
    __shared__ float ws[4];
    if ((tid & 31) == 0) ws[tid >> 5] = s;
    __syncthreads();
    if (tid == 0) out[b] = ws[0] + ws[1] + ws[2] + ws[3] + fc_b[0];
}

// -------- launch -------------------------------------------------------------
extern "C" void kernel_launch(void* const* d_in, const int* in_sizes, int n_in,
                              void* d_out, int out_size) {
    const float* x   = (const float*)d_in[0];
    const float* Ui  = (const float*)d_in[1];
    const float* Vi  = (const float*)d_in[2];
    const float* bi  = (const float*)d_in[3];
    const float* Uf  = (const float*)d_in[4];
    const float* Vf  = (const float*)d_in[5];
    const float* bf  = (const float*)d_in[6];
    const float* Uh  = (const float*)d_in[7];
    const float* Vh  = (const float*)d_in[8];
    const float* bh  = (const float*)d_in[9];
    const float* Uo  = (const float*)d_in[10];
    const float* Vo  = (const float*)d_in[11];
    const float* bo  = (const float*)d_in[12];
    const float* fcw = (const float*)d_in[13];
    const float* fcb = (const float*)d_in[14];
    float* out = (float*)d_out;

    cudaFuncSetAttribute(lstm_rec_kernel,
                         cudaFuncAttributeMaxDynamicSharedMemorySize, REC_SMEM_BYTES);

    reset_kernel<<<64, 256>>>();
    dim3 gx(G4 / 64, (BB * TT) / 128);
    xproj_kernel<<<gx, 256>>>(x, Ui, Uf, Uh, Uo, bi, bf, bh, bo);
    lstm_rec_kernel<<<NCTA, 256, REC_SMEM_BYTES>>>(Vi, Vf, Vh, Vo);
    fc_kernel<<<BB, 128>>>(fcw, fcb, out);
}

// round 6
// speedup vs baseline: 3.8132x; 3.8132x over previous
#include <cuda_runtime.h>
#include <cstdint>

#define BB 64
#define TT 1024
#define II 256
#define HH 512
#define G4 2048
#define NCTA 128          // persistent CTAs, 1/SM (big smem) -> co-resident on 152 SMs
#define NC 16             // gate columns per CTA (4 h-cols x 4 gates)
#define VT_S 516          // smem strides == 4 (mod 32) -> conflict-free fragments
#define HS_S 516
#define GS_S 18
#define REC_SMEM_FLOATS (NC*VT_S + 64*HS_S + 2*64*GS_S)
#define REC_SMEM_BYTES (REC_SMEM_FLOATS * 4)

// -------- global scratch (static device memory; no runtime allocation) -----
__device__ float g_xproj[(size_t)BB * TT * G4];   // [t*64+b][2048], bias folded
__device__ float g_hbuf[2][BB * HH];              // h ping-pong, tf32-pre-rounded
__device__ int   g_cnt;                            // monotonic arrival counter

// -------- helpers -----------------------------------------------------------
__device__ __forceinline__ float tf32r(float f) {
    unsigned u; asm("cvt.rna.tf32.f32 %0, %1;" : "=r"(u) : "f"(f));
    return __uint_as_float(u);
}
__device__ __forceinline__ unsigned fb(float f) { return __float_as_uint(f); }

__device__ __forceinline__ void mma_tf32(float* c,
    unsigned a0, unsigned a1, unsigned a2, unsigned a3, unsigned b0, unsigned b1) {
    asm volatile(
        "mma.sync.aligned.m16n8k8.row.col.f32.tf32.tf32.f32 "
        "{%0,%1,%2,%3},{%4,%5,%6,%7},{%8,%9},{%0,%1,%2,%3};"
        : "+f"(c[0]), "+f"(c[1]), "+f"(c[2]), "+f"(c[3])
        : "r"(a0), "r"(a1), "r"(a2), "r"(a3), "r"(b0), "r"(b1));
}
__device__ __forceinline__ int ld_acq(const int* p) {
    int v; asm volatile("ld.acquire.gpu.s32 %0, [%1];" : "=r"(v) : "l"(p) : "memory");
    return v;
}
__device__ __forceinline__ void red_rel_add(int* p, int v) {
    asm volatile("red.release.gpu.global.add.s32 [%0], %1;" :: "l"(p), "r"(v) : "memory");
}
__device__ __forceinline__ void cp_async16(uint32_t s, const void* g) {
    asm volatile("cp.async.cg.shared.global [%0], [%1], 16;" :: "r"(s), "l"(g));
}
__device__ __forceinline__ void cp_async_wait_all() {
    asm volatile("cp.async.commit_group;\n\tcp.async.wait_group 0;" ::: "memory");
}
__device__ __forceinline__ float fsig(float x) {
    return 1.0f / (1.0f + __expf(-x));
}

// -------- reset (state reinitialized on every graph replay) -----------------
__global__ void reset_kernel() {
    int tid = threadIdx.x + blockIdx.x * blockDim.x;
    for (int i = tid; i < BB * HH; i += blockDim.x * gridDim.x) g_hbuf[0][i] = 0.0f;
    if (tid == 0) g_cnt = 0;
}

// -------- phase 1: g_xproj[r][n] = x @ [U_i|U_f|U_h|U_o] + b ---------------
__global__ void __launch_bounds__(256) xproj_kernel(
    const float* __restrict__ x,
    const float* __restrict__ Ui, const float* __restrict__ Uf,
    const float* __restrict__ Uh, const float* __restrict__ Uo,
    const float* __restrict__ bi, const float* __restrict__ bf,
    const float* __restrict__ bh, const float* __restrict__ bo)
{
    __shared__ float As[128 * 36];
    __shared__ float Bs[32 * 72];
    __shared__ float bias_s[64];

    const int tid = threadIdx.x;
    const int n0 = blockIdx.x * 64;
    const int m0 = blockIdx.y * 128;
    const int q  = n0 >> 9;
    const int c0 = n0 & 511;

    const float* Uq = (q == 0) ? Ui : (q == 1) ? Uf : (q == 2) ? Uh : Uo;
    const float* bq = (q == 0) ? bi : (q == 1) ? bf : (q == 2) ? bh : bo;
    if (tid < 64) bias_s[tid] = bq[c0 + tid];

    const int w = tid >> 5, lane = tid & 31, g = lane >> 2, tig = lane & 3;
    const int warpM = w >> 1, warpN = w & 1;

    const int arow = tid >> 1, ahalf = tid & 1;
    const int r  = m0 + arow;
    const int bbi = r & 63, tti = r >> 6;
    const float* xrow = x + ((size_t)bbi * TT + tti) * II;
    const int brow = tid >> 3, bcol8 = (tid & 7) * 8;

    float acc[2][4][4] = {};

    for (int kc = 0; kc < 8; ++kc) {
        const int k0 = kc * 32;
        #pragma unroll
        for (int i = 0; i < 4; ++i) {
            float4 v = *(const float4*)(xrow + k0 + ahalf * 16 + i * 4);
            int off = arow * 36 + ahalf * 16 + i * 4;
            As[off+0] = tf32r(v.x); As[off+1] = tf32r(v.y);
            As[off+2] = tf32r(v.z); As[off+3] = tf32r(v.w);
        }
        #pragma unroll
        for (int i = 0; i < 2; ++i) {
            float4 v = *(const float4*)(Uq + (size_t)(k0 + brow) * HH + c0 + bcol8 + i * 4);
            int off = brow * 72 + bcol8 + i * 4;
            Bs[off+0] = tf32r(v.x); Bs[off+1] = tf32r(v.y);
            Bs[off+2] = tf32r(v.z); Bs[off+3] = tf32r(v.w);
        }
        __syncthreads();

        #pragma unroll
        for (int kk = 0; kk < 32; kk += 8) {
            unsigned a[2][4];
            #pragma unroll
            for (int i2 = 0; i2 < 2; ++i2) {
                int rb = warpM * 32 + i2 * 16;
                a[i2][0] = fb(As[(rb + g    ) * 36 + kk + tig]);
                a[i2][1] = fb(As[(rb + g + 8) * 36 + kk + tig]);
                a[i2][2] = fb(As[(rb + g    ) * 36 + kk + tig + 4]);
                a[i2][3] = fb(As[(rb + g + 8) * 36 + kk + tig + 4]);
            }
            #pragma unroll
            for (int nt = 0; nt < 4; ++nt) {
                int nn = warpN * 32 + nt * 8 + g;
                unsigned b0 = fb(Bs[(kk + tig    ) * 72 + nn]);
                unsigned b1 = fb(Bs[(kk + tig + 4) * 72 + nn]);
                mma_tf32(acc[0][nt], a[0][0], a[0][1], a[0][2], a[0][3], b0, b1);
                mma_tf32(acc[1][nt], a[1][0], a[1][1], a[1][2], a[1][3], b0, b1);
            }
        }
        __syncthreads();
    }

    #pragma unroll
    for (int i2 = 0; i2 < 2; ++i2) {
        #pragma unroll
        for (int nt = 0; nt < 4; ++nt) {
            int coll = warpN * 32 + nt * 8 + 2 * tig;
            float b0v = bias_s[coll], b1v = bias_s[coll + 1];
            int row0 = m0 + warpM * 32 + i2 * 16 + g;
            *(float2*)&g_xproj[(size_t)row0 * G4 + n0 + coll] =
                make_float2(acc[i2][nt][0] + b0v, acc[i2][nt][1] + b1v);
            *(float2*)&g_xproj[(size_t)(row0 + 8) * G4 + n0 + coll] =
                make_float2(acc[i2][nt][2] + b0v, acc[i2][nt][3] + b1v);
        }
    }
}

// -------- phase 2: persistent recurrence ------------------------------------
// 8 warps = 4 M-warps x 2 K-halves. Warp tile 16M x 16N, K=256 each.
// Counter barrier: at step t wait cnt >= NCTA*t; add 1 at end of step.
__global__ void __launch_bounds__(256, 1) lstm_rec_kernel(
    const float* __restrict__ Vi, const float* __restrict__ Vf,
    const float* __restrict__ Vh, const float* __restrict__ Vo)
{
    extern __shared__ float sm[];
    float* Vt = sm;                   // [16][516] tf32 V slice, [n][k]
    float* hs = Vt + NC * VT_S;       // [64][516] staged h (already tf32)
    float* gs = hs + 64 * HS_S;       // [2][64][18] partial-gate exchange

    const int tid = threadIdx.x, cta = blockIdx.x;
    const int hc0 = cta * 4;
    const int w = tid >> 5, lane = tid & 31, g = lane >> 2, tig = lane & 3;
    const int mw = w & 3, kh = w >> 2;

    // load this CTA's V slice once (tf32-rounded), layout [n][k]
    {
        const float* Vq[4] = { Vi, Vf, Vh, Vo };
        for (int idx = tid; idx < NC * HH; idx += 256) {
            int n = idx >> 9, k = idx & 511;
            Vt[n * VT_S + k] = tf32r(Vq[n >> 2][(size_t)k * HH + hc0 + (n & 3)]);
        }
    }
    __syncthreads();

    const int sb = tid >> 2, shc = tid & 3;          // this thread's (batch,hcol)
    const int r0 = tid >> 7, col4 = (tid & 127) * 4; // cp.async staging map
    const uint32_t hs_u32 = (uint32_t)__cvta_generic_to_shared(hs);
    float c_state = 0.0f;

    const float* Abase = hs + (mw * 16) * HS_S + kh * 256;
    const float* Bbase = Vt + kh * 256;
    float* gsp = gs + kh * (64 * GS_S);

    for (int t = 0; t < TT; ++t) {
        // prefetch xproj (DRAM, independent of h -> overlaps the spin)
        float xp[4];
        {
            const float* xb = g_xproj + ((size_t)t * BB + sb) * G4 + hc0 + shc;
            #pragma unroll
            for (int q2 = 0; q2 < 4; ++q2) xp[q2] = __ldg(xb + q2 * HH);
        }

        // wait for all CTAs to have published h_t
        if (t > 0 && tid == 0) {
            const int want = NCTA * t;
            while (ld_acq(&g_cnt) < want) { }
        }
        __syncthreads();

        // stage h_t (already tf32) via cp.async, fully coalesced 16B chunks
        {
            const float* hb = g_hbuf[t & 1];
            #pragma unroll
            for (int it = 0; it < 32; ++it) {
                int row = r0 + it * 2;
                cp_async16(hs_u32 + (uint32_t)(row * HS_S + col4) * 4u,
                           hb + row * HH + col4);
            }
            cp_async_wait_all();
        }
        __syncthreads();

        // gates_hV partials: warp (mw, kh), tile 16M x 16N over K half
        {
            float acc[2][2][4] = {};   // [nt][even/odd][4]
            #pragma unroll 4
            for (int kk = 0; kk < 256; kk += 8) {
                const int par = (kk >> 3) & 1;
                unsigned a0 = fb(Abase[(g    ) * HS_S + kk + tig]);
                unsigned a1 = fb(Abase[(g + 8) * HS_S + kk + tig]);
                unsigned a2 = fb(Abase[(g    ) * HS_S + kk + tig + 4]);
                unsigned a3 = fb(Abase[(g + 8) * HS_S + kk + tig + 4]);
                #pragma unroll
                for (int nt = 0; nt < 2; ++nt) {
                    unsigned b0 = fb(Bbase[(nt * 8 + g) * VT_S + kk + tig]);
                    unsigned b1 = fb(Bbase[(nt * 8 + g) * VT_S + kk + tig + 4]);
                    mma_tf32(acc[nt][par], a0, a1, a2, a3, b0, b1);
                }
            }
            #pragma unroll
            for (int nt = 0; nt < 2; ++nt) {
                int col = nt * 8 + 2 * tig;
                *(float2*)&gsp[(mw * 16 + g    ) * GS_S + col] =
                    make_float2(acc[nt][0][0] + acc[nt][1][0],
                                acc[nt][0][1] + acc[nt][1][1]);
                *(float2*)&gsp[(mw * 16 + g + 8) * GS_S + col] =
                    make_float2(acc[nt][0][2] + acc[nt][1][2],
                                acc[nt][0][3] + acc[nt][1][3]);
            }
        }
        __syncthreads();

        // elementwise gate update; c in register; h written tf32-pre-rounded
        {
            const float* g0 = gs + sb * GS_S + shc;
            const float* g1 = g0 + 64 * GS_S;
            float gi = g0[0]  + g1[0]  + xp[0];
            float gf = g0[4]  + g1[4]  + xp[1];
            float gg = g0[8]  + g1[8]  + xp[2];
            float go = g0[12] + g1[12] + xp[3];
            float it = fsig(gi), ft = fsig(gf), ot = fsig(go);
            float gt = tanhf(gg);
            c_state = ft * c_state + it * gt;
            g_hbuf[(t + 1) & 1][sb * HH + hc0 + shc] = tf32r(ot * tanhf(c_state));
        }
        __syncthreads();
        if (tid == 0) red_rel_add(&g_cnt, 1);
    }
}

// -------- phase 3: out[b] = h_last . fc_w + fc_b ----------------------------
__global__ void fc_kernel(const float* __restrict__ fc_w,
                          const float* __restrict__ fc_b, float* out) {
    int b = blockIdx.x, tid = threadIdx.x;
    const float* h = g_hbuf[0] + b * HH;   // h_1024 lives in buf[(1023+1)&1] = buf[0]
    float s = 0.0f;
    for (int k = tid; k < HH; k += 128) s += h[k] * fc_w[k];
    #pragma unroll
    for (int o = 16; o; o >>= 1) s += __shfl_down_sync(0xFFFFFFFFu, s, o);
    __shared__ float ws[4];
    if ((tid & 31) == 0) ws[tid >> 5] = s;
    __syncthreads();
    if (tid == 0) out[b] = ws[0] + ws[1] + ws[2] + ws[3] + fc_b[0];
}

// -------- launch -------------------------------------------------------------
extern "C" void kernel_launch(void* const* d_in, const int* in_sizes, int n_in,
                              void* d_out, int out_size) {
    const float* x   = (const float*)d_in[0];
    const float* Ui  = (const float*)d_in[1];
    const float* Vi  = (const float*)d_in[2];
    const float* bi  = (const float*)d_in[3];
    const float* Uf  = (const float*)d_in[4];
    const float* Vf  = (const float*)d_in[5];
    const float* bf  = (const float*)d_in[6];
    const float* Uh  = (const float*)d_in[7];
    const float* Vh  = (const float*)d_in[8];
    const float* bh  = (const float*)d_in[9];
    const float* Uo  = (const float*)d_in[10];
    const float* Vo  = (const float*)d_in[11];
    const float* bo  = (const float*)d_in[12];
    const float* fcw = (const float*)d_in[13];
    const float* fcb = (const float*)d_in[14];
    float* out = (float*)d_out;

    cudaFuncSetAttribute(lstm_rec_kernel,
                         cudaFuncAttributeMaxDynamicSharedMemorySize, REC_SMEM_BYTES);

    reset_kernel<<<64, 256>>>();
    dim3 gx(G4 / 64, (BB * TT) / 128);
    xproj_kernel<<<gx, 256>>>(x, Ui, Uf, Uh, Uo, bi, bf, bh, bo);
    lstm_rec_kernel<<<NCTA, 256, REC_SMEM_BYTES>>>(Vi, Vf, Vh, Vo);
    fc_kernel<<<BB, 128>>>(fcw, fcb, out);
}